// round 3
// baseline (speedup 1.0000x reference)
#include <cuda_runtime.h>

#define CIN 256
#define CK  8      // input-channel chunk per smem stage
#define PXT 128    // pixels per block tile
#define COT 64     // output channels per block tile

typedef unsigned long long u64;

// packed fp32x2 FMA: acc = a*b + acc (only reachable via PTX on sm_103a)
#define FMA2(acc, a, b) \
    asm("fma.rn.f32x2 %0, %1, %2, %0;" : "+l"(acc) : "l"(a), "l"(b))
#define PACK2(d, lo, hi) \
    asm("mov.b64 %0, {%1, %2};" : "=l"(d) : "f"(lo), "f"(hi))
#define UNPACK2(lo, hi, s) \
    asm("mov.b64 {%0, %1}, %2;" : "=f"(lo), "=f"(hi) : "l"(s))

// Scratch ping-pong buffers (largest level: 16*256*64*64 floats = 64 MiB each)
__device__ float g_bufA[16UL * 256 * 64 * 64];
__device__ float g_bufB[16UL * 256 * 64 * 64];
// Fused box(4)+ctr(1) prediction weights/bias
__device__ float g_w5[5 * 256 * 9];
__device__ float g_b5[8];

__global__ void pack5_kernel(const float* __restrict__ wb, const float* __restrict__ bb,
                             const float* __restrict__ wc, const float* __restrict__ bc) {
    int i = blockIdx.x * blockDim.x + threadIdx.x;
    const int n4 = 4 * 256 * 9;
    const int n5 = 5 * 256 * 9;
    if (i < n4)        g_w5[i] = wb[i];
    else if (i < n5)   g_w5[i] = wc[i - n4];
    if (i < 4)         g_b5[i] = bb[i];
    else if (i == 4)   g_b5[4] = bc[0];
}

// 3x3 SAME conv, Cin=256, stride 1, packed-f32x2 math.
// Block: 256 threads -> 64 Cout x 128 pixels. Thread: 4 Cout x 8 pixels (4 f32x2 pairs).
template <bool RELU, bool TO_OUT>
__global__ __launch_bounds__(256)
void conv3x3_kernel(const float* __restrict__ x, const float* __restrict__ w,
                    const float* __restrict__ bias, float* __restrict__ y,
                    int Cout, int H, int Wd, int row_off, int co_off)
{
    const int HW = H * Wd;
    const int R  = PXT / Wd + 2;   // input rows needed (with halo)
    const int SW = Wd + 4;         // padded smem row stride (multiple of 4 floats)

    // weights stored pre-duplicated: each u64 = (w, w); odd stride 73 avoids conflicts
    __shared__ __align__(16) u64   w2_s[COT * 73];   // 37376 B
    __shared__ __align__(16) float x_s[2176];        // [ci][R][SW], max 8*4*68 = 8704 B

    const int tid = threadIdx.x;
    const int pg  = tid & 15;   // pixel group 0..15 (8 px each)
    const int cg  = tid >> 4;   // cout group 0..15 (4 co each, stride 16)
    const int b   = blockIdx.z;
    const int P0      = blockIdx.x * PXT;
    const int co_base = blockIdx.y * COT;
    const int y0  = P0 / Wd;
    const int p_start = pg * 8;
    const int gyl = p_start / Wd;   // local row of this thread's pixel group
    const int gx0 = p_start % Wd;   // leftmost padded col needed by this group

    u64 acc[4][4];   // [co][pixel-pair]; 0ULL == (+0.f, +0.f)
#pragma unroll
    for (int i = 0; i < 4; i++)
#pragma unroll
        for (int j = 0; j < 4; j++) acc[i][j] = 0ULL;

    const int xload_n = CK * R * (Wd + 2);
    const float* xb = x + (size_t)b * CIN * HW;

    for (int cic = 0; cic < CIN; cic += CK) {
        __syncthreads();
        // ---- stage weights duplicated into u64 pairs
        for (int idx = tid; idx < COT * CK * 9; idx += 256) {
            int co_l = idx / (CK * 9);
            int rem  = idx % (CK * 9);
            int ci   = rem / 9;
            int tap  = rem % 9;
            int co_g = co_base + co_l;
            float v  = 0.f;
            if (co_g < Cout) v = w[((size_t)co_g * CIN + cic + ci) * 9 + tap];
            u64 p;
            PACK2(p, v, v);
            w2_s[co_l * 73 + ci * 9 + tap] = p;
        }
        // ---- stage input tile with halo + zero padding
        for (int idx = tid; idx < xload_n; idx += 256) {
            int ci  = idx / (R * (Wd + 2));
            int rem = idx % (R * (Wd + 2));
            int r   = rem / (Wd + 2);
            int c   = rem % (Wd + 2);
            int gy  = y0 - 1 + r;
            int gx  = c - 1;
            float v = 0.f;
            if (gy >= 0 && gy < H && gx >= 0 && gx < Wd)
                v = xb[(size_t)(cic + ci) * HW + gy * Wd + gx];
            x_s[(ci * R + r) * SW + c] = v;
        }
        __syncthreads();

#pragma unroll 1
        for (int ci = 0; ci < CK; ci++) {
            const float* xp = &x_s[ci * R * SW];
#pragma unroll
            for (int dy = 0; dy < 3; dy++) {
                const float* rp = &xp[(gyl + dy) * SW + gx0];
                float4 a0 = *(const float4*)(rp);
                float4 a1 = *(const float4*)(rp + 4);
                float2 a2 = *(const float2*)(rp + 8);
                float xr[10];
                xr[0] = a0.x; xr[1] = a0.y; xr[2] = a0.z; xr[3] = a0.w;
                xr[4] = a1.x; xr[5] = a1.y; xr[6] = a1.z; xr[7] = a1.w;
                xr[8] = a2.x; xr[9] = a2.y;

                // 5 even-aligned pairs + 4 odd-aligned pairs cover dx=0,1,2
                u64 pe[5], po[4];
#pragma unroll
                for (int k = 0; k < 5; k++) PACK2(pe[k], xr[2 * k], xr[2 * k + 1]);
#pragma unroll
                for (int k = 0; k < 4; k++) PACK2(po[k], xr[2 * k + 1], xr[2 * k + 2]);

                u64 w0[4], w1[4], w2v[4];
#pragma unroll
                for (int i = 0; i < 4; i++) {
                    int base = (cg + i * 16) * 73 + ci * 9 + dy * 3;
                    w0[i]  = w2_s[base];
                    w1[i]  = w2_s[base + 1];
                    w2v[i] = w2_s[base + 2];
                }
#pragma unroll
                for (int i = 0; i < 4; i++) {
#pragma unroll
                    for (int j = 0; j < 4; j++) FMA2(acc[i][j], w0[i],  pe[j]);
#pragma unroll
                    for (int j = 0; j < 4; j++) FMA2(acc[i][j], w1[i],  po[j]);
#pragma unroll
                    for (int j = 0; j < 4; j++) FMA2(acc[i][j], w2v[i], pe[j + 1]);
                }
            }
        }
    }

    // ---- epilogue
#pragma unroll
    for (int i = 0; i < 4; i++) {
        int co = co_base + cg + i * 16;
        if (co >= Cout) continue;
        float bv = bias[co];
        float v[8];
#pragma unroll
        for (int j = 0; j < 4; j++) {
            float lo, hi;
            UNPACK2(lo, hi, acc[i][j]);
            lo += bv; hi += bv;
            if (RELU) { lo = fmaxf(lo, 0.f); hi = fmaxf(hi, 0.f); }
            v[2 * j] = lo; v[2 * j + 1] = hi;
        }
        if (!TO_OUT) {
            float* yp = y + ((size_t)b * Cout + co) * HW + P0 + p_start;
            *(float4*)(yp)     = make_float4(v[0], v[1], v[2], v[3]);
            *(float4*)(yp + 4) = make_float4(v[4], v[5], v[6], v[7]);
        } else {
#pragma unroll
            for (int j = 0; j < 8; j++) {
                int p = P0 + p_start + j;
                y[((size_t)b * 5376 + row_off + p) * 85 + co_off + co] = v[j];
            }
        }
    }
}

extern "C" void kernel_launch(void* const* d_in, const int* in_sizes, int n_in,
                              void* d_out, int out_size)
{
    // metadata order: feat_p3, feat_p4, feat_p5, stem_cls_w, stem_cls_b,
    //                 stem_box_w, stem_box_b, pred_cls_w, pred_cls_b,
    //                 pred_box_w, pred_box_b, pred_ctr_w, pred_ctr_b
    const float* f[13];
    for (int i = 0; i < 13; i++) f[i] = (const float*)d_in[i];
    float* out = (float*)d_out;

    float *A, *B, *W5, *B5;
    cudaGetSymbolAddress((void**)&A,  g_bufA);
    cudaGetSymbolAddress((void**)&B,  g_bufB);
    cudaGetSymbolAddress((void**)&W5, g_w5);
    cudaGetSymbolAddress((void**)&B5, g_b5);

    // fuse box(4) + ctr(1) pred weights into one 5-channel conv
    pack5_kernel<<<(5 * 256 * 9 + 255) / 256, 256>>>(f[9], f[10], f[11], f[12]);

    struct Lv { const float* feat; int H, W, row_off; };
    const Lv lvls[3] = { { f[0], 64, 64, 0 },
                         { f[1], 32, 32, 4096 },
                         { f[2], 16, 16, 5120 } };

    const size_t WSTEM = (size_t)CIN * CIN * 9;  // one stem conv's weights
    for (int l = 0; l < 3; l++) {
        const Lv& L = lvls[l];
        const int HW = L.H * L.W;
        dim3 gs(HW / PXT, (256 + COT - 1) / COT, 16);   // stem grids
        dim3 gc(HW / PXT, (80 + COT - 1) / COT, 16);    // cls pred grid
        dim3 g5(HW / PXT, 1, 16);                       // box+ctr pred grid

        // ---- cls branch: feat -> A -> B -> A -> B -> out[:, :, 0:80]
        conv3x3_kernel<true, false><<<gs, 256>>>(L.feat, f[3] + 0 * WSTEM, f[4] + 0 * 256, A, 256, L.H, L.W, 0, 0);
        conv3x3_kernel<true, false><<<gs, 256>>>(A,      f[3] + 1 * WSTEM, f[4] + 1 * 256, B, 256, L.H, L.W, 0, 0);
        conv3x3_kernel<true, false><<<gs, 256>>>(B,      f[3] + 2 * WSTEM, f[4] + 2 * 256, A, 256, L.H, L.W, 0, 0);
        conv3x3_kernel<true, false><<<gs, 256>>>(A,      f[3] + 3 * WSTEM, f[4] + 3 * 256, B, 256, L.H, L.W, 0, 0);
        conv3x3_kernel<false, true><<<gc, 256>>>(B, f[7], f[8], out, 80, L.H, L.W, L.row_off, 0);

        // ---- box branch: feat -> A -> B -> A -> B -> out[:, :, 80:85]
        conv3x3_kernel<true, false><<<gs, 256>>>(L.feat, f[5] + 0 * WSTEM, f[6] + 0 * 256, A, 256, L.H, L.W, 0, 0);
        conv3x3_kernel<true, false><<<gs, 256>>>(A,      f[5] + 1 * WSTEM, f[6] + 1 * 256, B, 256, L.H, L.W, 0, 0);
        conv3x3_kernel<true, false><<<gs, 256>>>(B,      f[5] + 2 * WSTEM, f[6] + 2 * 256, A, 256, L.H, L.W, 0, 0);
        conv3x3_kernel<true, false><<<gs, 256>>>(A,      f[5] + 3 * WSTEM, f[6] + 3 * 256, B, 256, L.H, L.W, 0, 0);
        conv3x3_kernel<false, true><<<g5, 256>>>(B, W5, B5, out, 5, L.H, L.W, L.row_off, 80);
    }
}

// round 5
// speedup vs baseline: 2.6560x; 2.6560x over previous
#include <cuda_runtime.h>
#include <cuda_bf16.h>

typedef unsigned long long u64;
typedef unsigned int u32;
typedef __nv_bfloat16 bf16;

// ---------------- static device buffers (no allocation allowed) ----------------
#define PLANE (16ul * 4096 * 256)      // elems of one (hi or lo) activation plane
__device__ bf16 g_act0[2 * PLANE];     // feat planes   [hi | lo]
__device__ bf16 g_act1[2 * PLANE];     // ping
__device__ bf16 g_act2[2 * PLANE];     // pong
__device__ bf16 g_wsh[8ul * 9 * 256 * 256];   // stem weights hi: [branch*4+s][tap][co][ci]
__device__ bf16 g_wsl[8ul * 9 * 256 * 256];   // stem weights lo
__device__ bf16 g_wph[2ul * 9 * 128 * 256];   // pred weights hi: [set][tap][co(128 pad)][ci]
__device__ bf16 g_wpl[2ul * 9 * 128 * 256];
__device__ float g_b5[8];                      // fused box(4)+ctr(1) bias

// ---------------- helpers ----------------
__device__ __forceinline__ u32 cvta_smem(const void* p) {
    u32 a;
    asm("{ .reg .u64 t; cvta.to.shared.u64 t, %1; cvt.u32.u64 %0, t; }" : "=r"(a) : "l"(p));
    return a;
}
__device__ __forceinline__ u32 sw128(u32 o) { return o ^ ((o >> 3) & 0x70); }

#define LDSM4(r0, r1, r2, r3, addr) \
    asm volatile("ldmatrix.sync.aligned.m8n8.x4.shared.b16 {%0,%1,%2,%3}, [%4];" \
        : "=r"(r0), "=r"(r1), "=r"(r2), "=r"(r3) : "r"(addr))

#define MMA16816(d, a, b0, b1) \
    asm volatile("mma.sync.aligned.m16n8k16.row.col.f32.bf16.bf16.f32 " \
        "{%0,%1,%2,%3}, {%4,%5,%6,%7}, {%8,%9}, {%0,%1,%2,%3};" \
        : "+f"((d)[0]), "+f"((d)[1]), "+f"((d)[2]), "+f"((d)[3]) \
        : "r"((a)[0]), "r"((a)[1]), "r"((a)[2]), "r"((a)[3]), "r"(b0), "r"(b1))

__device__ __forceinline__ void bf16_split(float x, bf16& h, bf16& l) {
    h = __float2bfloat16(x);
    l = __float2bfloat16(x - __bfloat162float(h));
}

// ---------------- prepass: fp32 NCHW -> NHWC bf16 hi/lo planes ----------------
__global__ void to_planes(const float* __restrict__ in, bf16* __restrict__ hi,
                          bf16* __restrict__ lo, int logHW) {
    __shared__ float t[32][33];
    const int HW = 1 << logHW;
    int hw0 = blockIdx.x * 32, c0 = blockIdx.y * 32, b = blockIdx.z;
    int tx = threadIdx.x, ty = threadIdx.y;
    const float* ib = in + ((size_t)b * 256 + c0) * HW + hw0;
#pragma unroll
    for (int i = 0; i < 4; i++) t[ty + i * 8][tx] = ib[(size_t)(ty + i * 8) * HW + tx];
    __syncthreads();
#pragma unroll
    for (int i = 0; i < 4; i++) {
        int yy = ty + i * 8;
        float v = t[tx][yy];
        size_t o = ((((size_t)b << logHW) + hw0 + yy) << 8) + c0 + tx;
        bf16 h, l; bf16_split(v, h, l);
        hi[o] = h; lo[o] = l;
    }
}

// ---------------- prepass: stem weights -> per-tap hi/lo planes ----------------
__global__ void conv_stem_w(const float* __restrict__ w, bf16* __restrict__ dh,
                            bf16* __restrict__ dl) {
    int idx = blockIdx.x * 256 + threadIdx.x;   // layout: ((s*9+tap)<<16)|(co<<8)|ci
    int ci  = idx & 255;
    int co  = (idx >> 8) & 255;
    int st  = idx >> 16;
    int s = st / 9, tap = st % 9;
    float v = w[(((size_t)s * 256 + co) * 256 + ci) * 9 + tap];
    bf16 h, l; bf16_split(v, h, l);
    dh[idx] = h; dl[idx] = l;
}

// ---------------- prepass: pred weights (padded to 128 rows) ----------------
__global__ void conv_pred_w(const float* __restrict__ wA, int nA, const float* __restrict__ wB,
                            bf16* __restrict__ dh, bf16* __restrict__ dl) {
    int idx = blockIdx.x * 256 + threadIdx.x;   // layout: (tap<<15)|(co<<8)|ci
    int ci  = idx & 255;
    int co  = (idx >> 8) & 127;
    int tap = idx >> 15;
    float v = 0.f;
    if (co < nA)               v = wA[((size_t)co * 256 + ci) * 9 + tap];
    else if (wB && co == nA)   v = wB[(size_t)ci * 9 + tap];
    bf16 h, l; bf16_split(v, h, l);
    dh[idx] = h; dl[idx] = l;
}

__global__ void pack_b5(const float* bb, const float* bc) {
    int i = threadIdx.x;
    if (i < 4) g_b5[i] = bb[i];
    else if (i == 4) g_b5[4] = bc[0];
}

// ---------------- main conv: mma.sync bf16 3-product implicit GEMM ------------
// CTA 256 thr / 8 warps; tile 128 cout x 128 px; warp tile 64x32.
// Smem stage: A hi/lo (128x64ci) + B hi/lo (128x64ci) = 64 KB, SW128 swizzle.
// MODE 0: stem (bias+ReLU -> bf16 hi/lo NHWC planes)
// MODE 1: pred (bias -> fp32 (B,5376,85) head layout)
#define SMEMSZ 65536
template <int MODE>
__global__ __launch_bounds__(256, 2)
void conv_mma(const bf16* __restrict__ whi, const bf16* __restrict__ wlo, int wM,
              const bf16* __restrict__ xhi, const bf16* __restrict__ xlo,
              const float* __restrict__ bias,
              bf16* __restrict__ ohi, bf16* __restrict__ olo,
              float* __restrict__ opred,
              int logW, int logHW, int row_off, int co_off, int coutActual)
{
    extern __shared__ __align__(1024) char smem[];
    const u32 sb = cvta_smem(smem);
    const int tid  = threadIdx.x;
    const int wid  = tid >> 5, lane = tid & 31;
    const int mw   = wid & 1;          // 0/1 : co block of 64
    const int nw   = wid >> 1;         // 0..3: px block of 32
    const int b    = blockIdx.z;
    const int P0   = blockIdx.x * 128;
    const int co_base = blockIdx.y * 128;
    const int Wd = 1 << logW;
    const int Hh = 1 << (logHW - logW);

    float acc[4][4][4];
#pragma unroll
    for (int i = 0; i < 4; i++)
#pragma unroll
        for (int j = 0; j < 4; j++)
#pragma unroll
            for (int e = 0; e < 4; e++) acc[i][j][e] = 0.f;

    // per-lane ldmatrix address components (byte offsets within a 128x128B tile)
    const u32 aRow = mw * 64 + (lane & 15);
    const u32 aCol = (lane >> 4) << 4;
    const u32 bRow = nw * 32 + (lane & 7) + ((lane >> 4) & 1) * 8;
    const u32 bCol = ((lane >> 3) & 1) << 4;

    for (int k = 0; k < 36; k++) {
        int tap = k >> 2, ci0 = (k & 3) << 6;
        int dy = tap / 3 - 1, dx = tap % 3 - 1;
        __syncthreads();
        // ---- stage A (weights) hi/lo : 128 rows x 128B each
#pragma unroll
        for (int i = 0; i < 8; i++) {
            int idx = tid + (i << 8);
            int lof = idx >> 10;
            int r   = (idx >> 3) & 127;
            int s   = idx & 7;
            const bf16* src = (lof ? wlo : whi)
                + (((size_t)(tap * wM + co_base + r)) << 8) + ci0 + (s << 3);
            uint4 v = *(const uint4*)src;
            *(uint4*)(smem + (lof << 14) + sw128((r << 7) | (s << 4))) = v;
        }
        // ---- stage B (shifted activations) hi/lo, zero at borders
#pragma unroll
        for (int i = 0; i < 8; i++) {
            int idx = tid + (i << 8);
            int lof = idx >> 10;
            int r   = (idx >> 3) & 127;
            int s   = idx & 7;
            int p   = P0 + r;
            int y = p >> logW, x = p & (Wd - 1);
            int sy = y + dy, sx = x + dx;
            uint4 v = make_uint4(0u, 0u, 0u, 0u);
            if ((unsigned)sy < (unsigned)Hh && (unsigned)sx < (unsigned)Wd) {
                const bf16* src = (lof ? xlo : xhi)
                    + (((((size_t)b << logHW) + ((size_t)sy << logW) + sx)) << 8) + ci0 + (s << 3);
                v = *(const uint4*)src;
            }
            *(uint4*)(smem + 32768 + (lof << 14) + sw128((r << 7) | (s << 4))) = v;
        }
        __syncthreads();

        // ---- 3 products: (Ahi,Bhi), (Ahi,Blo), (Alo,Bhi)
#pragma unroll
        for (int p = 0; p < 3; p++) {
            const u32 Ab = sb + ((p == 2) ? 16384u : 0u);
            const u32 Bb = sb + 32768u + ((p == 1) ? 16384u : 0u);
#pragma unroll
            for (int k16 = 0; k16 < 4; k16++) {
                const u32 kb = k16 << 5;
                u32 af[4][4], bg[2][4];
#pragma unroll
                for (int i = 0; i < 4; i++)
                    LDSM4(af[i][0], af[i][1], af[i][2], af[i][3],
                          Ab + sw128(((aRow + i * 16) << 7) + kb + aCol));
#pragma unroll
                for (int g = 0; g < 2; g++)
                    LDSM4(bg[g][0], bg[g][1], bg[g][2], bg[g][3],
                          Bb + sw128(((bRow + g * 16) << 7) + kb + bCol));
#pragma unroll
                for (int i = 0; i < 4; i++)
#pragma unroll
                    for (int j = 0; j < 4; j++)
                        MMA16816(acc[i][j], af[i], bg[j >> 1][2 * (j & 1)], bg[j >> 1][2 * (j & 1) + 1]);
            }
        }
    }

    // ---- epilogue straight from registers
#pragma unroll
    for (int i = 0; i < 4; i++) {
        int cl0 = mw * 64 + i * 16 + (lane >> 2);  // local cout rows for regs {0,1} / {2,3}
        int cl1 = cl0 + 8;
        float bv0, bv1;
        if (MODE == 0) { bv0 = bias[co_base + cl0]; bv1 = bias[co_base + cl1]; }
        else { bv0 = (cl0 < coutActual) ? bias[cl0] : 0.f;
               bv1 = (cl1 < coutActual) ? bias[cl1] : 0.f; }
#pragma unroll
        for (int j = 0; j < 4; j++) {
            int px = P0 + nw * 32 + j * 8 + ((lane & 3) << 1);
#pragma unroll
            for (int e = 0; e < 4; e++) {
                int cl = (e < 2) ? cl0 : cl1;
                float bv = (e < 2) ? bv0 : bv1;
                int p = px + (e & 1);
                float xv = acc[i][j][e] + bv;
                if (MODE == 0) {
                    xv = fmaxf(xv, 0.f);
                    bf16 h, l; bf16_split(xv, h, l);
                    size_t o = ((((size_t)b << logHW) + p) << 8) + co_base + cl;
                    ohi[o] = h; olo[o] = l;
                } else if (cl < coutActual) {
                    opred[((size_t)b * 5376 + row_off + p) * 85 + co_off + cl] = xv;
                }
            }
        }
    }
}

// ---------------- host launcher ----------------
extern "C" void kernel_launch(void* const* d_in, const int* in_sizes, int n_in,
                              void* d_out, int out_size)
{
    const float* f[13];
    for (int i = 0; i < 13; i++) f[i] = (const float*)d_in[i];
    float* out = (float*)d_out;

    bf16 *a0, *a1, *a2, *wsh, *wsl, *wph, *wpl;
    float* b5;
    cudaGetSymbolAddress((void**)&a0, g_act0);
    cudaGetSymbolAddress((void**)&a1, g_act1);
    cudaGetSymbolAddress((void**)&a2, g_act2);
    cudaGetSymbolAddress((void**)&wsh, g_wsh);
    cudaGetSymbolAddress((void**)&wsl, g_wsl);
    cudaGetSymbolAddress((void**)&wph, g_wph);
    cudaGetSymbolAddress((void**)&wpl, g_wpl);
    cudaGetSymbolAddress((void**)&b5, g_b5);

    cudaFuncSetAttribute(conv_mma<0>, cudaFuncAttributeMaxDynamicSharedMemorySize, SMEMSZ);
    cudaFuncSetAttribute(conv_mma<1>, cudaFuncAttributeMaxDynamicSharedMemorySize, SMEMSZ);

    // weight/bias prepasses
    pack_b5<<<1, 8>>>(f[10], f[12]);
    conv_stem_w<<<9216, 256>>>(f[3], wsh, wsl);                                  // cls stems
    conv_stem_w<<<9216, 256>>>(f[5], wsh + 36ul * 65536, wsl + 36ul * 65536);    // box stems
    conv_pred_w<<<1152, 256>>>(f[7], 80, nullptr, wph, wpl);                     // cls pred
    conv_pred_w<<<1152, 256>>>(f[9], 4, f[11], wph + 9ul * 32768, wpl + 9ul * 32768); // box+ctr

    struct Lv { const float* feat; int logW, logHW, row_off; };
    const Lv lv[3] = { { f[0], 6, 12, 0 }, { f[1], 5, 10, 4096 }, { f[2], 4, 8, 5120 } };

    for (int l = 0; l < 3; l++) {
        const int logW = lv[l].logW, logHW = lv[l].logHW, row_off = lv[l].row_off;
        const int HW = 1 << logHW;
        to_planes<<<dim3(HW / 32, 8, 16), dim3(32, 8)>>>(lv[l].feat, a0, a0 + PLANE, logHW);

        dim3 gs(HW / 128, 2, 16), gp(HW / 128, 1, 16);
        for (int br = 0; br < 2; br++) {
            const bf16* swh = wsh + (size_t)br * 36 * 65536;
            const bf16* swl = wsl + (size_t)br * 36 * 65536;
            const float* sbp = br ? f[6] : f[4];
            // stem: feat -> a1 -> a2 -> a1 -> a2
            conv_mma<0><<<gs, 256, SMEMSZ>>>(swh + 0ul * 9 * 65536, swl + 0ul * 9 * 65536, 256,
                a0, a0 + PLANE, sbp + 0, a1, a1 + PLANE, nullptr, logW, logHW, 0, 0, 256);
            conv_mma<0><<<gs, 256, SMEMSZ>>>(swh + 1ul * 9 * 65536, swl + 1ul * 9 * 65536, 256,
                a1, a1 + PLANE, sbp + 256, a2, a2 + PLANE, nullptr, logW, logHW, 0, 0, 256);
            conv_mma<0><<<gs, 256, SMEMSZ>>>(swh + 2ul * 9 * 65536, swl + 2ul * 9 * 65536, 256,
                a2, a2 + PLANE, sbp + 512, a1, a1 + PLANE, nullptr, logW, logHW, 0, 0, 256);
            conv_mma<0><<<gs, 256, SMEMSZ>>>(swh + 3ul * 9 * 65536, swl + 3ul * 9 * 65536, 256,
                a1, a1 + PLANE, sbp + 768, a2, a2 + PLANE, nullptr, logW, logHW, 0, 0, 256);
            if (br == 0)
                conv_mma<1><<<gp, 256, SMEMSZ>>>(wph, wpl, 128,
                    a2, a2 + PLANE, f[8], nullptr, nullptr, out, logW, logHW, row_off, 0, 80);
            else
                conv_mma<1><<<gp, 256, SMEMSZ>>>(wph + 9ul * 32768, wpl + 9ul * 32768, 128,
                    a2, a2 + PLANE, b5, nullptr, nullptr, out, logW, logHW, row_off, 80, 5);
        }
    }
}

// round 7
// speedup vs baseline: 4.1768x; 1.5726x over previous
#include <cuda_runtime.h>
#include <cuda_bf16.h>

typedef unsigned long long u64;
typedef unsigned int u32;
typedef __nv_bfloat16 bf16;

// ---------------- static device buffers (no allocation allowed) ----------------
#define PLANE (16ul * 4096 * 256)      // elems of one (hi or lo) activation plane
__device__ __align__(256) bf16 g_act0[2 * PLANE];     // feat planes   [hi | lo]
__device__ __align__(256) bf16 g_act1[2 * PLANE];     // ping
__device__ __align__(256) bf16 g_act2[2 * PLANE];     // pong
__device__ __align__(256) bf16 g_wsh[8ul * 9 * 256 * 256];   // stem w hi: [branch*4+s][tap][co][ci]
__device__ __align__(256) bf16 g_wsl[8ul * 9 * 256 * 256];   // stem w lo
__device__ __align__(256) bf16 g_wph[2ul * 9 * 128 * 256];   // pred w hi: [set][tap][co(128 pad)][ci]
__device__ __align__(256) bf16 g_wpl[2ul * 9 * 128 * 256];
__device__ float g_b5[8];                      // fused box(4)+ctr(1) bias

// ---------------- helpers ----------------
__device__ __forceinline__ u32 cvta_smem(const void* p) {
    u32 a;
    asm("{ .reg .u64 t; cvta.to.shared.u64 t, %1; cvt.u32.u64 %0, t; }" : "=r"(a) : "l"(p));
    return a;
}
__device__ __forceinline__ u32 sw64(u32 o) { return o ^ ((o >> 3) & 0x30); }

#define LDSM4(r0, r1, r2, r3, addr) \
    asm volatile("ldmatrix.sync.aligned.m8n8.x4.shared.b16 {%0,%1,%2,%3}, [%4];" \
        : "=r"(r0), "=r"(r1), "=r"(r2), "=r"(r3) : "r"(addr))

#define MMA16816(d, a, b0, b1) \
    asm volatile("mma.sync.aligned.m16n8k16.row.col.f32.bf16.bf16.f32 " \
        "{%0,%1,%2,%3}, {%4,%5,%6,%7}, {%8,%9}, {%0,%1,%2,%3};" \
        : "+f"((d)[0]), "+f"((d)[1]), "+f"((d)[2]), "+f"((d)[3]) \
        : "r"((a)[0]), "r"((a)[1]), "r"((a)[2]), "r"((a)[3]), "r"(b0), "r"(b1))

#define CPA_CG(d, s)     asm volatile("cp.async.cg.shared.global [%0], [%1], 16;" :: "r"(d), "l"(s))
#define CPA_CA(d, s, n)  asm volatile("cp.async.ca.shared.global [%0], [%1], 16, %2;" :: "r"(d), "l"(s), "r"(n))
#define CPA_COMMIT       asm volatile("cp.async.commit_group;" ::: "memory")
#define CPA_WAIT1        asm volatile("cp.async.wait_group 1;" ::: "memory")
#define CPA_WAIT0        asm volatile("cp.async.wait_group 0;" ::: "memory")

__device__ __forceinline__ void bf16_split(float x, bf16& h, bf16& l) {
    h = __float2bfloat16(x);
    l = __float2bfloat16(x - __bfloat162float(h));
}

// ---------------- prepass: fp32 NCHW -> NHWC bf16 hi/lo planes ----------------
__global__ void to_planes(const float* __restrict__ in, bf16* __restrict__ hi,
                          bf16* __restrict__ lo, int logHW) {
    __shared__ float t[32][33];
    const int HW = 1 << logHW;
    int hw0 = blockIdx.x * 32, c0 = blockIdx.y * 32, b = blockIdx.z;
    int tx = threadIdx.x, ty = threadIdx.y;
    const float* ib = in + ((size_t)b * 256 + c0) * HW + hw0;
#pragma unroll
    for (int i = 0; i < 4; i++) t[ty + i * 8][tx] = ib[(size_t)(ty + i * 8) * HW + tx];
    __syncthreads();
#pragma unroll
    for (int i = 0; i < 4; i++) {
        int yy = ty + i * 8;
        float v = t[tx][yy];
        size_t o = ((((size_t)b << logHW) + hw0 + yy) << 8) + c0 + tx;
        bf16 h, l; bf16_split(v, h, l);
        hi[o] = h; lo[o] = l;
    }
}

// ---------------- prepass: stem weights -> per-tap hi/lo planes ----------------
__global__ void conv_stem_w(const float* __restrict__ w, bf16* __restrict__ dh,
                            bf16* __restrict__ dl) {
    int idx = blockIdx.x * 256 + threadIdx.x;   // layout: ((s*9+tap)<<16)|(co<<8)|ci
    int ci  = idx & 255;
    int co  = (idx >> 8) & 255;
    int st  = idx >> 16;
    int s = st / 9, tap = st % 9;
    float v = w[(((size_t)s * 256 + co) * 256 + ci) * 9 + tap];
    bf16 h, l; bf16_split(v, h, l);
    dh[idx] = h; dl[idx] = l;
}

// ---------------- prepass: pred weights (padded to 128 rows) ----------------
__global__ void conv_pred_w(const float* __restrict__ wA, int nA, const float* __restrict__ wB,
                            bf16* __restrict__ dh, bf16* __restrict__ dl) {
    int idx = blockIdx.x * 256 + threadIdx.x;   // layout: (tap<<15)|(co<<8)|ci
    int ci  = idx & 255;
    int co  = (idx >> 8) & 127;
    int tap = idx >> 15;
    float v = 0.f;
    if (co < nA)               v = wA[((size_t)co * 256 + ci) * 9 + tap];
    else if (wB && co == nA)   v = wB[(size_t)ci * 9 + tap];
    bf16 h, l; bf16_split(v, h, l);
    dh[idx] = h; dl[idx] = l;
}

__global__ void pack_b5(const float* bb, const float* bc) {
    int i = threadIdx.x;
    if (i < 4) g_b5[i] = bb[i];
    else if (i == 4) g_b5[4] = bc[0];
}

// ---------------- main conv: cp.async-pipelined mma.sync 3-product GEMM -------
// CTA 256 thr / 8 warps; tile 128 cout x 128 px; warp tile 64x32.
// 72 chunks of (tap, 32ci). Stage/buffer: A hi/lo 16KB + B hi/lo 16KB = 32KB,
// double-buffered (64KB), SW64 swizzle on 64B rows. 2 CTAs/SM.
#define SMEMSZ 65536
template <int MODE>
__global__ __launch_bounds__(256, 2)
void conv_mma(const bf16* __restrict__ whi, const bf16* __restrict__ wlo, int wM,
              const bf16* __restrict__ xhi, const bf16* __restrict__ xlo,
              const float* __restrict__ bias,
              bf16* __restrict__ ohi, bf16* __restrict__ olo,
              float* __restrict__ opred,
              int logW, int logHW, int row_off, int co_off, int coutActual)
{
    extern __shared__ __align__(1024) char smem[];
    const u32 sb = cvta_smem(smem);
    const int tid  = threadIdx.x;
    const int wid  = tid >> 5, lane = tid & 31;
    const int mw   = wid & 1;          // 0/1 : co block of 64
    const int nw   = wid >> 1;         // 0..3: px block of 32
    const int b    = blockIdx.z;
    const int P0   = blockIdx.x * 128;
    const int co_base = blockIdx.y * 128;
    const int Wd = 1 << logW;
    const int Hh = 1 << (logHW - logW);

    float acc[4][4][4];
#pragma unroll
    for (int i = 0; i < 4; i++)
#pragma unroll
        for (int j = 0; j < 4; j++)
#pragma unroll
            for (int e = 0; e < 4; e++) acc[i][j][e] = 0.f;

    // ldmatrix lane addressing (within 64B-row tiles)
    const u32 aRow = mw * 64 + (lane & 15);
    const u32 aCol = (lane >> 4) << 4;
    const u32 bRow = nw * 32 + (lane & 7) + ((lane >> 4) & 1) * 8;
    const u32 bCol = ((lane >> 3) & 1) << 4;

    // ---- chunk staging via cp.async (all 256 threads) ----
    auto stage_chunk = [&](int k, u32 bufoff) {
        int tap = k >> 3, ci0 = (k & 7) << 5;
        int dy = tap / 3 - 1, dx = tap % 3 - 1;
        // A (weights) hi/lo: 2 planes x 128 rows x 64B
#pragma unroll
        for (int i = 0; i < 4; i++) {
            int idx = tid + (i << 8);
            int lof = idx >> 9;
            int r   = (idx >> 2) & 127;
            int s   = idx & 3;
            const bf16* src = (lof ? wlo : whi)
                + (((size_t)(tap * wM + co_base + r)) << 8) + ci0 + (s << 3);
            u32 dst = sb + bufoff + ((u32)lof << 13) + sw64((r << 6) | (s << 4));
            CPA_CG(dst, src);
        }
        // B (activations) hi/lo: 2 planes x 128 px x 64B, zero-filled at borders
#pragma unroll
        for (int i = 0; i < 4; i++) {
            int idx = tid + (i << 8);
            int lof = idx >> 9;
            int r   = (idx >> 2) & 127;
            int s   = idx & 3;
            int p   = P0 + r;
            int y = p >> logW, x = p & (Wd - 1);
            int sy = y + dy, sx = x + dx;
            u32 ok = ((unsigned)sy < (unsigned)Hh && (unsigned)sx < (unsigned)Wd) ? 16u : 0u;
            int csy = ok ? sy : 0, csx = ok ? sx : 0;
            const bf16* src = (lof ? xlo : xhi)
                + (((((size_t)b << logHW) + ((size_t)csy << logW) + csx)) << 8) + ci0 + (s << 3);
            u32 dst = sb + bufoff + 16384u + ((u32)lof << 13) + sw64((r << 6) | (s << 4));
            CPA_CA(dst, src, ok);
        }
    };

    stage_chunk(0, 0); CPA_COMMIT;

    for (int k = 0; k < 72; k++) {
        u32 cur = (u32)(k & 1) * 32768u;
        if (k < 71) { stage_chunk(k + 1, (u32)((k + 1) & 1) * 32768u); CPA_COMMIT; CPA_WAIT1; }
        else        { CPA_WAIT0; }
        __syncthreads();

        const u32 Ah = sb + cur, Al = Ah + 8192u;
        const u32 Bh = sb + cur + 16384u, Bl = Bh + 8192u;
#pragma unroll
        for (int k16 = 0; k16 < 2; k16++) {
            const u32 kb = (u32)k16 << 5;
            u32 ah[4][4], al[4][4], bh[2][4], bl[2][4];
#pragma unroll
            for (int i = 0; i < 4; i++)
                LDSM4(ah[i][0], ah[i][1], ah[i][2], ah[i][3],
                      Ah + sw64(((aRow + i * 16) << 6) + kb + aCol));
#pragma unroll
            for (int g = 0; g < 2; g++)
                LDSM4(bh[g][0], bh[g][1], bh[g][2], bh[g][3],
                      Bh + sw64(((bRow + g * 16) << 6) + kb + bCol));
#pragma unroll
            for (int g = 0; g < 2; g++)
                LDSM4(bl[g][0], bl[g][1], bl[g][2], bl[g][3],
                      Bl + sw64(((bRow + g * 16) << 6) + kb + bCol));
            // products (Ah,Bh) and (Ah,Bl)
#pragma unroll
            for (int i = 0; i < 4; i++)
#pragma unroll
                for (int j = 0; j < 4; j++) {
                    MMA16816(acc[i][j], ah[i], bh[j >> 1][2 * (j & 1)], bh[j >> 1][2 * (j & 1) + 1]);
                    MMA16816(acc[i][j], ah[i], bl[j >> 1][2 * (j & 1)], bl[j >> 1][2 * (j & 1) + 1]);
                }
            // product (Al,Bh)
#pragma unroll
            for (int i = 0; i < 4; i++)
                LDSM4(al[i][0], al[i][1], al[i][2], al[i][3],
                      Al + sw64(((aRow + i * 16) << 6) + kb + aCol));
#pragma unroll
            for (int i = 0; i < 4; i++)
#pragma unroll
                for (int j = 0; j < 4; j++)
                    MMA16816(acc[i][j], al[i], bh[j >> 1][2 * (j & 1)], bh[j >> 1][2 * (j & 1) + 1]);
        }
        __syncthreads();
    }

    // ---- epilogue straight from registers
#pragma unroll
    for (int i = 0; i < 4; i++) {
        int cl0 = mw * 64 + i * 16 + (lane >> 2);
        int cl1 = cl0 + 8;
        float bv0, bv1;
        if (MODE == 0) { bv0 = bias[co_base + cl0]; bv1 = bias[co_base + cl1]; }
        else { bv0 = (cl0 < coutActual) ? bias[cl0] : 0.f;
               bv1 = (cl1 < coutActual) ? bias[cl1] : 0.f; }
#pragma unroll
        for (int j = 0; j < 4; j++) {
            int px = P0 + nw * 32 + j * 8 + ((lane & 3) << 1);
#pragma unroll
            for (int e = 0; e < 4; e++) {
                int cl = (e < 2) ? cl0 : cl1;
                float bv = (e < 2) ? bv0 : bv1;
                int p = px + (e & 1);
                float xv = acc[i][j][e] + bv;
                if (MODE == 0) {
                    xv = fmaxf(xv, 0.f);
                    bf16 h, l; bf16_split(xv, h, l);
                    size_t o = ((((size_t)b << logHW) + p) << 8) + co_base + cl;
                    ohi[o] = h; olo[o] = l;
                } else if (cl < coutActual) {
                    opred[((size_t)b * 5376 + row_off + p) * 85 + co_off + cl] = xv;
                }
            }
        }
    }
}

// ---------------- host launcher ----------------
extern "C" void kernel_launch(void* const* d_in, const int* in_sizes, int n_in,
                              void* d_out, int out_size)
{
    const float* f[13];
    for (int i = 0; i < 13; i++) f[i] = (const float*)d_in[i];
    float* out = (float*)d_out;

    bf16 *a0, *a1, *a2, *wsh, *wsl, *wph, *wpl;
    float* b5;
    cudaGetSymbolAddress((void**)&a0, g_act0);
    cudaGetSymbolAddress((void**)&a1, g_act1);
    cudaGetSymbolAddress((void**)&a2, g_act2);
    cudaGetSymbolAddress((void**)&wsh, g_wsh);
    cudaGetSymbolAddress((void**)&wsl, g_wsl);
    cudaGetSymbolAddress((void**)&wph, g_wph);
    cudaGetSymbolAddress((void**)&wpl, g_wpl);
    cudaGetSymbolAddress((void**)&b5, g_b5);

    cudaFuncSetAttribute(conv_mma<0>, cudaFuncAttributeMaxDynamicSharedMemorySize, SMEMSZ);
    cudaFuncSetAttribute(conv_mma<1>, cudaFuncAttributeMaxDynamicSharedMemorySize, SMEMSZ);

    // weight/bias prepasses
    pack_b5<<<1, 8>>>(f[10], f[12]);
    conv_stem_w<<<9216, 256>>>(f[3], wsh, wsl);                                  // cls stems
    conv_stem_w<<<9216, 256>>>(f[5], wsh + 36ul * 65536, wsl + 36ul * 65536);    // box stems
    conv_pred_w<<<1152, 256>>>(f[7], 80, nullptr, wph, wpl);                     // cls pred
    conv_pred_w<<<1152, 256>>>(f[9], 4, f[11], wph + 9ul * 32768, wpl + 9ul * 32768); // box+ctr

    struct Lv { const float* feat; int logW, logHW, row_off; };
    const Lv lv[3] = { { f[0], 6, 12, 0 }, { f[1], 5, 10, 4096 }, { f[2], 4, 8, 5120 } };

    for (int l = 0; l < 3; l++) {
        const int logW = lv[l].logW, logHW = lv[l].logHW, row_off = lv[l].row_off;
        const int HW = 1 << logHW;
        to_planes<<<dim3(HW / 32, 8, 16), dim3(32, 8)>>>(lv[l].feat, a0, a0 + PLANE, logHW);

        dim3 gs(HW / 128, 2, 16), gp(HW / 128, 1, 16);
        for (int br = 0; br < 2; br++) {
            const bf16* swh = wsh + (size_t)br * 36 * 65536;
            const bf16* swl = wsl + (size_t)br * 36 * 65536;
            const float* sbp = br ? f[6] : f[4];
            // stem: feat -> a1 -> a2 -> a1 -> a2
            conv_mma<0><<<gs, 256, SMEMSZ>>>(swh + 0ul * 9 * 65536, swl + 0ul * 9 * 65536, 256,
                a0, a0 + PLANE, sbp + 0, a1, a1 + PLANE, nullptr, logW, logHW, 0, 0, 256);
            conv_mma<0><<<gs, 256, SMEMSZ>>>(swh + 1ul * 9 * 65536, swl + 1ul * 9 * 65536, 256,
                a1, a1 + PLANE, sbp + 256, a2, a2 + PLANE, nullptr, logW, logHW, 0, 0, 256);
            conv_mma<0><<<gs, 256, SMEMSZ>>>(swh + 2ul * 9 * 65536, swl + 2ul * 9 * 65536, 256,
                a2, a2 + PLANE, sbp + 512, a1, a1 + PLANE, nullptr, logW, logHW, 0, 0, 256);
            conv_mma<0><<<gs, 256, SMEMSZ>>>(swh + 3ul * 9 * 65536, swl + 3ul * 9 * 65536, 256,
                a1, a1 + PLANE, sbp + 768, a2, a2 + PLANE, nullptr, logW, logHW, 0, 0, 256);
            if (br == 0)
                conv_mma<1><<<gp, 256, SMEMSZ>>>(wph, wpl, 128,
                    a2, a2 + PLANE, f[8], nullptr, nullptr, out, logW, logHW, row_off, 0, 80);
            else
                conv_mma<1><<<gp, 256, SMEMSZ>>>(wph + 9ul * 32768, wpl + 9ul * 32768, 128,
                    a2, a2 + PLANE, b5, nullptr, nullptr, out, logW, logHW, row_off, 80, 5);
        }
    }
}

// round 9
// speedup vs baseline: 5.7009x; 1.3649x over previous
#include <cuda_runtime.h>
#include <cuda_fp16.h>

typedef unsigned long long u64;
typedef unsigned int u32;
typedef __half fp16;

// ---------------- static device buffers (no allocation allowed) ----------------
#define PLANE (16ul * 4096 * 256)      // elems of one (hi or lo) activation plane
__device__ __align__(256) fp16 g_act0[2 * PLANE];     // feat planes   [hi | lo]
__device__ __align__(256) fp16 g_act1[2 * PLANE];     // ping
__device__ __align__(256) fp16 g_act2[2 * PLANE];     // pong
__device__ __align__(256) fp16 g_wsh[8ul * 9 * 256 * 256];   // stem w (fp16 hi): [branch*4+s][tap][co][ci]
__device__ __align__(256) fp16 g_wph[2ul * 9 * 128 * 256];   // pred w (fp16 hi): [set][tap][co(128 pad)][ci]
__device__ float g_b5[8];                      // fused box(4)+ctr(1) bias

// ---------------- helpers ----------------
__device__ __forceinline__ u32 cvta_smem(const void* p) {
    u32 a;
    asm("{ .reg .u64 t; cvta.to.shared.u64 t, %1; cvt.u32.u64 %0, t; }" : "=r"(a) : "l"(p));
    return a;
}
__device__ __forceinline__ u32 sw64(u32 o) { return o ^ ((o >> 3) & 0x30); }

#define LDSM4(r0, r1, r2, r3, addr) \
    asm volatile("ldmatrix.sync.aligned.m8n8.x4.shared.b16 {%0,%1,%2,%3}, [%4];" \
        : "=r"(r0), "=r"(r1), "=r"(r2), "=r"(r3) : "r"(addr))

#define MMA16816(d, a, b0, b1) \
    asm volatile("mma.sync.aligned.m16n8k16.row.col.f32.f16.f16.f32 " \
        "{%0,%1,%2,%3}, {%4,%5,%6,%7}, {%8,%9}, {%0,%1,%2,%3};" \
        : "+f"((d)[0]), "+f"((d)[1]), "+f"((d)[2]), "+f"((d)[3]) \
        : "r"((a)[0]), "r"((a)[1]), "r"((a)[2]), "r"((a)[3]), "r"(b0), "r"(b1))

#define CPA_CG(d, s)     asm volatile("cp.async.cg.shared.global [%0], [%1], 16;" :: "r"(d), "l"(s))
#define CPA_CA(d, s, n)  asm volatile("cp.async.ca.shared.global [%0], [%1], 16, %2;" :: "r"(d), "l"(s), "r"(n))
#define CPA_COMMIT       asm volatile("cp.async.commit_group;" ::: "memory")
#define CPA_WAIT1        asm volatile("cp.async.wait_group 1;" ::: "memory")
#define CPA_WAIT0        asm volatile("cp.async.wait_group 0;" ::: "memory")

__device__ __forceinline__ void fp16_split(float x, fp16& h, fp16& l) {
    h = __float2half_rn(x);
    l = __float2half_rn(x - __half2float(h));
}

// ---------------- prepass: fp32 NCHW -> NHWC fp16 hi/lo planes ----------------
__global__ void to_planes(const float* __restrict__ in, fp16* __restrict__ hi,
                          fp16* __restrict__ lo, int logHW) {
    __shared__ float t[32][33];
    const int HW = 1 << logHW;
    int hw0 = blockIdx.x * 32, c0 = blockIdx.y * 32, b = blockIdx.z;
    int tx = threadIdx.x, ty = threadIdx.y;
    const float* ib = in + ((size_t)b * 256 + c0) * HW + hw0;
#pragma unroll
    for (int i = 0; i < 4; i++) t[ty + i * 8][tx] = ib[(size_t)(ty + i * 8) * HW + tx];
    __syncthreads();
#pragma unroll
    for (int i = 0; i < 4; i++) {
        int yy = ty + i * 8;
        float v = t[tx][yy];
        size_t o = ((((size_t)b << logHW) + hw0 + yy) << 8) + c0 + tx;
        fp16 h, l; fp16_split(v, h, l);
        hi[o] = h; lo[o] = l;
    }
}

// ---------------- prepass: stem weights -> per-tap fp16 planes ----------------
__global__ void conv_stem_w(const float* __restrict__ w, fp16* __restrict__ dh) {
    int idx = blockIdx.x * 256 + threadIdx.x;   // layout: ((s*9+tap)<<16)|(co<<8)|ci
    int ci  = idx & 255;
    int co  = (idx >> 8) & 255;
    int st  = idx >> 16;
    int s = st / 9, tap = st % 9;
    dh[idx] = __float2half_rn(w[(((size_t)s * 256 + co) * 256 + ci) * 9 + tap]);
}

// ---------------- prepass: pred weights (padded to 128 rows) ----------------
__global__ void conv_pred_w(const float* __restrict__ wA, int nA, const float* __restrict__ wB,
                            fp16* __restrict__ dh) {
    int idx = blockIdx.x * 256 + threadIdx.x;   // layout: (tap<<15)|(co<<8)|ci
    int ci  = idx & 255;
    int co  = (idx >> 8) & 127;
    int tap = idx >> 15;
    float v = 0.f;
    if (co < nA)               v = wA[((size_t)co * 256 + ci) * 9 + tap];
    else if (wB && co == nA)   v = wB[(size_t)ci * 9 + tap];
    dh[idx] = __float2half_rn(v);
}

__global__ void pack_b5(const float* bb, const float* bc) {
    int i = threadIdx.x;
    if (i < 4) g_b5[i] = bb[i];
    else if (i == 4) g_b5[4] = bc[0];
}

// ---------------- main conv: 3-stage cp.async fp16 2-product GEMM -------------
// CTA 256 thr / 8 warps; tile 128 cout x 128 px; warp tile 64x32.
// 72 chunks of (tap, 32ci). Stage = A 8KB + Bh 8KB + Bl 8KB = 24KB, 3-stage ring.
#define STAGE 24576
#define SMEMSZ (3 * STAGE)
template <int MODE>
__global__ __launch_bounds__(256, 2)
void conv_mma(const fp16* __restrict__ wh, int wM,
              const fp16* __restrict__ xhi, const fp16* __restrict__ xlo,
              const float* __restrict__ bias,
              fp16* __restrict__ ohi, fp16* __restrict__ olo,
              float* __restrict__ opred,
              int logW, int logHW, int row_off, int co_off, int coutActual)
{
    extern __shared__ __align__(1024) char smem[];
    const u32 sb = cvta_smem(smem);
    const int tid  = threadIdx.x;
    const int wid  = tid >> 5, lane = tid & 31;
    const int mw   = wid & 1;          // 0/1 : co block of 64
    const int nw   = wid >> 1;         // 0..3: px block of 32
    const int b    = blockIdx.z;
    const int P0   = blockIdx.x * 128;
    const int co_base = blockIdx.y * 128;
    const int Wd = 1 << logW;
    const int Hh = 1 << (logHW - logW);

    float acc[4][4][4];
#pragma unroll
    for (int i = 0; i < 4; i++)
#pragma unroll
        for (int j = 0; j < 4; j++)
#pragma unroll
            for (int e = 0; e < 4; e++) acc[i][j][e] = 0.f;

    // ldmatrix lane addressing (within 64B-row tiles)
    const u32 aRow = mw * 64 + (lane & 15);
    const u32 aCol = (lane >> 4) << 4;
    const u32 bRow = nw * 32 + (lane & 7) + ((lane >> 4) & 1) * 8;
    const u32 bCol = ((lane >> 3) & 1) << 4;

    // ---- chunk staging via cp.async (all 256 threads; 6 cp.async each) ----
    auto stage_chunk = [&](int k, u32 bufoff) {
        int tap = k >> 3, ci0 = (k & 7) << 5;
        int dy = tap / 3 - 1, dx = tap % 3 - 1;
        // A (weights fp16): 128 rows x 64B
#pragma unroll
        for (int i = 0; i < 2; i++) {
            int idx = tid + (i << 8);
            int r   = idx >> 2;
            int s   = idx & 3;
            const fp16* src = wh + (((size_t)(tap * wM + co_base + r)) << 8) + ci0 + (s << 3);
            u32 dst = sb + bufoff + sw64((r << 6) | (s << 4));
            CPA_CG(dst, src);
        }
        // B (activations) hi/lo: 2 planes x 128 px x 64B, zero-filled at borders
#pragma unroll
        for (int i = 0; i < 4; i++) {
            int idx = tid + (i << 8);
            int lof = idx >> 9;
            int r   = (idx >> 2) & 127;
            int s   = idx & 3;
            int p   = P0 + r;
            int y = p >> logW, x = p & (Wd - 1);
            int sy = y + dy, sx = x + dx;
            u32 ok = ((unsigned)sy < (unsigned)Hh && (unsigned)sx < (unsigned)Wd) ? 16u : 0u;
            int csy = ok ? sy : 0, csx = ok ? sx : 0;
            const fp16* src = (lof ? xlo : xhi)
                + (((((size_t)b << logHW) + ((size_t)csy << logW) + csx)) << 8) + ci0 + (s << 3);
            u32 dst = sb + bufoff + 8192u + ((u32)lof << 13) + sw64((r << 6) | (s << 4));
            CPA_CA(dst, src, ok);
        }
    };

    stage_chunk(0, 0); CPA_COMMIT;
    stage_chunk(1, STAGE); CPA_COMMIT;

    for (int k = 0; k < 72; k++) {
        u32 cur = (u32)(k % 3) * STAGE;
        if (k < 71) CPA_WAIT1; else CPA_WAIT0;
        __syncthreads();   // chunk k visible to all; all warps done consuming k-1
        if (k < 70) { stage_chunk(k + 2, (u32)((k + 2) % 3) * STAGE); CPA_COMMIT; }

        const u32 Ah = sb + cur;
        const u32 Bh = Ah + 8192u, Bl = Ah + 16384u;
#pragma unroll
        for (int k16 = 0; k16 < 2; k16++) {
            const u32 kb = (u32)k16 << 5;
            u32 ah[4][4], bh[2][4], bl[2][4];
#pragma unroll
            for (int i = 0; i < 4; i++)
                LDSM4(ah[i][0], ah[i][1], ah[i][2], ah[i][3],
                      Ah + sw64(((aRow + i * 16) << 6) + kb + aCol));
#pragma unroll
            for (int g = 0; g < 2; g++)
                LDSM4(bh[g][0], bh[g][1], bh[g][2], bh[g][3],
                      Bh + sw64(((bRow + g * 16) << 6) + kb + bCol));
#pragma unroll
            for (int g = 0; g < 2; g++)
                LDSM4(bl[g][0], bl[g][1], bl[g][2], bl[g][3],
                      Bl + sw64(((bRow + g * 16) << 6) + kb + bCol));
#pragma unroll
            for (int i = 0; i < 4; i++)
#pragma unroll
                for (int j = 0; j < 4; j++) {
                    MMA16816(acc[i][j], ah[i], bh[j >> 1][2 * (j & 1)], bh[j >> 1][2 * (j & 1) + 1]);
                    MMA16816(acc[i][j], ah[i], bl[j >> 1][2 * (j & 1)], bl[j >> 1][2 * (j & 1) + 1]);
                }
        }
    }

    // ---- epilogue straight from registers
#pragma unroll
    for (int i = 0; i < 4; i++) {
        int cl0 = mw * 64 + i * 16 + (lane >> 2);
        int cl1 = cl0 + 8;
        float bv0, bv1;
        if (MODE == 0) { bv0 = bias[co_base + cl0]; bv1 = bias[co_base + cl1]; }
        else { bv0 = (cl0 < coutActual) ? bias[cl0] : 0.f;
               bv1 = (cl1 < coutActual) ? bias[cl1] : 0.f; }
#pragma unroll
        for (int j = 0; j < 4; j++) {
            int px = P0 + nw * 32 + j * 8 + ((lane & 3) << 1);
#pragma unroll
            for (int e = 0; e < 4; e++) {
                int cl = (e < 2) ? cl0 : cl1;
                float bv = (e < 2) ? bv0 : bv1;
                int p = px + (e & 1);
                float xv = acc[i][j][e] + bv;
                if (MODE == 0) {
                    xv = fmaxf(xv, 0.f);
                    fp16 h, l; fp16_split(xv, h, l);
                    size_t o = ((((size_t)b << logHW) + p) << 8) + co_base + cl;
                    ohi[o] = h; olo[o] = l;
                } else if (cl < coutActual) {
                    opred[((size_t)b * 5376 + row_off + p) * 85 + co_off + cl] = xv;
                }
            }
        }
    }
}

// ---------------- host launcher ----------------
extern "C" void kernel_launch(void* const* d_in, const int* in_sizes, int n_in,
                              void* d_out, int out_size)
{
    const float* f[13];
    for (int i = 0; i < 13; i++) f[i] = (const float*)d_in[i];
    float* out = (float*)d_out;

    fp16 *a0, *a1, *a2, *wsh, *wph;
    float* b5;
    cudaGetSymbolAddress((void**)&a0, g_act0);
    cudaGetSymbolAddress((void**)&a1, g_act1);
    cudaGetSymbolAddress((void**)&a2, g_act2);
    cudaGetSymbolAddress((void**)&wsh, g_wsh);
    cudaGetSymbolAddress((void**)&wph, g_wph);
    cudaGetSymbolAddress((void**)&b5, g_b5);

    cudaFuncSetAttribute(conv_mma<0>, cudaFuncAttributeMaxDynamicSharedMemorySize, SMEMSZ);
    cudaFuncSetAttribute(conv_mma<1>, cudaFuncAttributeMaxDynamicSharedMemorySize, SMEMSZ);

    // weight/bias prepasses
    pack_b5<<<1, 8>>>(f[10], f[12]);
    conv_stem_w<<<9216, 256>>>(f[3], wsh);                       // cls stems
    conv_stem_w<<<9216, 256>>>(f[5], wsh + 36ul * 65536);        // box stems
    conv_pred_w<<<1152, 256>>>(f[7], 80, nullptr, wph);          // cls pred
    conv_pred_w<<<1152, 256>>>(f[9], 4, f[11], wph + 9ul * 32768); // box+ctr

    struct Lv { const float* feat; int logW, logHW, row_off; };
    const Lv lv[3] = { { f[0], 6, 12, 0 }, { f[1], 5, 10, 4096 }, { f[2], 4, 8, 5120 } };

    for (int l = 0; l < 3; l++) {
        const int logW = lv[l].logW, logHW = lv[l].logHW, row_off = lv[l].row_off;
        const int HW = 1 << logHW;
        to_planes<<<dim3(HW / 32, 8, 16), dim3(32, 8)>>>(lv[l].feat, a0, a0 + PLANE, logHW);

        dim3 gs(HW / 128, 2, 16), gp(HW / 128, 1, 16);
        for (int br = 0; br < 2; br++) {
            const fp16* swh = wsh + (size_t)br * 36 * 65536;
            const float* sbp = br ? f[6] : f[4];
            // stem: feat -> a1 -> a2 -> a1 -> a2
            conv_mma<0><<<gs, 256, SMEMSZ>>>(swh + 0ul * 9 * 65536, 256,
                a0, a0 + PLANE, sbp + 0, a1, a1 + PLANE, nullptr, logW, logHW, 0, 0, 256);
            conv_mma<0><<<gs, 256, SMEMSZ>>>(swh + 1ul * 9 * 65536, 256,
                a1, a1 + PLANE, sbp + 256, a2, a2 + PLANE, nullptr, logW, logHW, 0, 0, 256);
            conv_mma<0><<<gs, 256, SMEMSZ>>>(swh + 2ul * 9 * 65536, 256,
                a2, a2 + PLANE, sbp + 512, a1, a1 + PLANE, nullptr, logW, logHW, 0, 0, 256);
            conv_mma<0><<<gs, 256, SMEMSZ>>>(swh + 3ul * 9 * 65536, 256,
                a1, a1 + PLANE, sbp + 768, a2, a2 + PLANE, nullptr, logW, logHW, 0, 0, 256);
            if (br == 0)
                conv_mma<1><<<gp, 256, SMEMSZ>>>(wph, 128,
                    a2, a2 + PLANE, f[8], nullptr, nullptr, out, logW, logHW, row_off, 0, 80);
            else
                conv_mma<1><<<gp, 256, SMEMSZ>>>(wph + 9ul * 32768, 128,
                    a2, a2 + PLANE, b5, nullptr, nullptr, out, logW, logHW, row_off, 80, 5);
        }
    }
}

// round 10
// speedup vs baseline: 6.6713x; 1.1702x over previous
#include <cuda_runtime.h>
#include <cuda_fp16.h>

typedef unsigned long long u64;
typedef unsigned int u32;
typedef __half fp16;

// ---------------- static device buffers (no allocation allowed) ----------------
#define PLANE (16ul * 4096 * 256)      // elems of one (hi or lo) activation plane
__device__ __align__(256) fp16 g_act0[2 * PLANE];     // input feat planes [hi | lo]
__device__ __align__(256) fp16 g_c1[2 * PLANE];       // cls ping
__device__ __align__(256) fp16 g_c2[2 * PLANE];       // cls pong
__device__ __align__(256) fp16 g_x1[2 * PLANE];       // box ping
__device__ __align__(256) fp16 g_x2[2 * PLANE];       // box pong
__device__ __align__(256) fp16 g_wsh[8ul * 9 * 256 * 256];   // stem w: [branch*4+s][tap][co][ci]
__device__ __align__(256) fp16 g_wph[2ul * 9 * 128 * 256];   // pred w: [set][tap][co(128 pad)][ci]
__device__ float g_b5[8];                      // fused box(4)+ctr(1) bias

// ---------------- helpers ----------------
__device__ __forceinline__ u32 cvta_smem(const void* p) {
    u32 a;
    asm("{ .reg .u64 t; cvta.to.shared.u64 t, %1; cvt.u32.u64 %0, t; }" : "=r"(a) : "l"(p));
    return a;
}
__device__ __forceinline__ u32 sw64(u32 o) { return o ^ ((o >> 3) & 0x30); }

#define LDSM4(r0, r1, r2, r3, addr) \
    asm volatile("ldmatrix.sync.aligned.m8n8.x4.shared.b16 {%0,%1,%2,%3}, [%4];" \
        : "=r"(r0), "=r"(r1), "=r"(r2), "=r"(r3) : "r"(addr))

#define MMA16816(d, a, b0, b1) \
    asm volatile("mma.sync.aligned.m16n8k16.row.col.f32.f16.f16.f32 " \
        "{%0,%1,%2,%3}, {%4,%5,%6,%7}, {%8,%9}, {%0,%1,%2,%3};" \
        : "+f"((d)[0]), "+f"((d)[1]), "+f"((d)[2]), "+f"((d)[3]) \
        : "r"((a)[0]), "r"((a)[1]), "r"((a)[2]), "r"((a)[3]), "r"(b0), "r"(b1))

#define CPA_CG(d, s)     asm volatile("cp.async.cg.shared.global [%0], [%1], 16;" :: "r"(d), "l"(s))
#define CPA_CA(d, s, n)  asm volatile("cp.async.ca.shared.global [%0], [%1], 16, %2;" :: "r"(d), "l"(s), "r"(n))
#define CPA_COMMIT       asm volatile("cp.async.commit_group;" ::: "memory")
#define CPA_WAIT1        asm volatile("cp.async.wait_group 1;" ::: "memory")
#define CPA_WAIT0        asm volatile("cp.async.wait_group 0;" ::: "memory")

__device__ __forceinline__ void fp16_split(float x, fp16& h, fp16& l) {
    h = __float2half_rn(x);
    l = __float2half_rn(x - __half2float(h));
}

// ---------------- prepass: fp32 NCHW -> NHWC fp16 hi/lo planes ----------------
__global__ void to_planes(const float* __restrict__ in, fp16* __restrict__ hi,
                          fp16* __restrict__ lo, int logHW) {
    __shared__ float t[32][33];
    const int HW = 1 << logHW;
    int hw0 = blockIdx.x * 32, c0 = blockIdx.y * 32, b = blockIdx.z;
    int tx = threadIdx.x, ty = threadIdx.y;
    const float* ib = in + ((size_t)b * 256 + c0) * HW + hw0;
#pragma unroll
    for (int i = 0; i < 4; i++) t[ty + i * 8][tx] = ib[(size_t)(ty + i * 8) * HW + tx];
    __syncthreads();
#pragma unroll
    for (int i = 0; i < 4; i++) {
        int yy = ty + i * 8;
        float v = t[tx][yy];
        size_t o = ((((size_t)b << logHW) + hw0 + yy) << 8) + c0 + tx;
        fp16 h, l; fp16_split(v, h, l);
        hi[o] = h; lo[o] = l;
    }
}

// ---------------- prepass: stem weights -> per-tap fp16 planes ----------------
__global__ void conv_stem_w(const float* __restrict__ w, fp16* __restrict__ dh) {
    int idx = blockIdx.x * 256 + threadIdx.x;   // layout: ((s*9+tap)<<16)|(co<<8)|ci
    int ci  = idx & 255;
    int co  = (idx >> 8) & 255;
    int st  = idx >> 16;
    int s = st / 9, tap = st % 9;
    dh[idx] = __float2half_rn(w[(((size_t)s * 256 + co) * 256 + ci) * 9 + tap]);
}

// ---------------- prepass: pred weights (padded to 128 rows) ----------------
__global__ void conv_pred_w(const float* __restrict__ wA, int nA, const float* __restrict__ wB,
                            fp16* __restrict__ dh) {
    int idx = blockIdx.x * 256 + threadIdx.x;   // layout: (tap<<15)|(co<<8)|ci
    int ci  = idx & 255;
    int co  = (idx >> 8) & 127;
    int tap = idx >> 15;
    float v = 0.f;
    if (co < nA)               v = wA[((size_t)co * 256 + ci) * 9 + tap];
    else if (wB && co == nA)   v = wB[(size_t)ci * 9 + tap];
    dh[idx] = __float2half_rn(v);
}

__global__ void pack_b5(const float* bb, const float* bc) {
    int i = threadIdx.x;
    if (i < 4) g_b5[i] = bb[i];
    else if (i == 4) g_b5[4] = bc[0];
}

// ---------------- main conv: 3-stage cp.async fp16 2-product GEMM -------------
// Branch-merged: blockIdx.z = b + 16*branch. Chunks ordered tap-fastest
// (tap = k%9, ci = k/9) so activation lines hit L1 across the 9 taps.
// MODE 0: stem (bias+ReLU -> fp16 hi/lo planes, coalesced via smem transpose)
// MODE 1: pred (bias -> fp32 (B,5376,85); set 0 = cls(80), set 1 = box+ctr(5))
#define STAGE 24576
#define SMEMSZ (3 * STAGE)
template <int MODE>
__global__ __launch_bounds__(256, 2)
void conv_mma(const fp16* __restrict__ w0, const fp16* __restrict__ w1, int wM,
              const fp16* __restrict__ x0h, const fp16* __restrict__ x0l,
              const fp16* __restrict__ x1h, const fp16* __restrict__ x1l,
              const float* __restrict__ bias0, const float* __restrict__ bias1,
              fp16* __restrict__ o0h, fp16* __restrict__ o0l,
              fp16* __restrict__ o1h, fp16* __restrict__ o1l,
              float* __restrict__ opred,
              int logW, int logHW, int row_off)
{
    extern __shared__ __align__(1024) char smem[];
    const u32 sb = cvta_smem(smem);
    const int tid  = threadIdx.x;
    const int wid  = tid >> 5, lane = tid & 31;
    const int mw   = wid & 1;          // 0/1 : co block of 64
    const int nw   = wid >> 1;         // 0..3: px block of 32
    const int br   = blockIdx.z >> 4;  // branch/set
    const int b    = blockIdx.z & 15;
    const int P0   = blockIdx.x * 128;
    const int co_base = blockIdx.y * 128;
    const int Wd = 1 << logW;
    const int Hh = 1 << (logHW - logW);

    const fp16* wh  = br ? w1 : w0;
    const fp16* xhi = br ? x1h : x0h;
    const fp16* xlo = br ? x1l : x0l;

    float acc[4][4][4];
#pragma unroll
    for (int i = 0; i < 4; i++)
#pragma unroll
        for (int j = 0; j < 4; j++)
#pragma unroll
            for (int e = 0; e < 4; e++) acc[i][j][e] = 0.f;

    // ldmatrix lane addressing (within 64B-row tiles)
    const u32 aRow = mw * 64 + (lane & 15);
    const u32 aCol = (lane >> 4) << 4;
    const u32 bRow = nw * 32 + (lane & 7) + ((lane >> 4) & 1) * 8;
    const u32 bCol = ((lane >> 3) & 1) << 4;

    // ---- chunk staging via cp.async (all 256 threads; 6 cp.async each) ----
    auto stage_chunk = [&](int k, u32 bufoff) {
        int ci_i = k / 9;
        int tap  = k - ci_i * 9;       // tap-fastest
        int ci0  = ci_i << 5;
        int dy = tap / 3 - 1, dx = tap % 3 - 1;
        // A (weights fp16): 128 rows x 64B
#pragma unroll
        for (int i = 0; i < 2; i++) {
            int idx = tid + (i << 8);
            int r   = idx >> 2;
            int s   = idx & 3;
            const fp16* src = wh + (((size_t)(tap * wM + co_base + r)) << 8) + ci0 + (s << 3);
            u32 dst = sb + bufoff + sw64((r << 6) | (s << 4));
            CPA_CG(dst, src);
        }
        // B (activations) hi/lo: 2 planes x 128 px x 64B, zero-filled at borders
#pragma unroll
        for (int i = 0; i < 4; i++) {
            int idx = tid + (i << 8);
            int lof = idx >> 9;
            int r   = (idx >> 2) & 127;
            int s   = idx & 3;
            int p   = P0 + r;
            int y = p >> logW, x = p & (Wd - 1);
            int sy = y + dy, sx = x + dx;
            u32 ok = ((unsigned)sy < (unsigned)Hh && (unsigned)sx < (unsigned)Wd) ? 16u : 0u;
            int csy = ok ? sy : 0, csx = ok ? sx : 0;
            const fp16* src = (lof ? xlo : xhi)
                + (((((size_t)b << logHW) + ((size_t)csy << logW) + csx)) << 8) + ci0 + (s << 3);
            u32 dst = sb + bufoff + 8192u + ((u32)lof << 13) + sw64((r << 6) | (s << 4));
            CPA_CA(dst, src, ok);
        }
    };

    stage_chunk(0, 0); CPA_COMMIT;
    stage_chunk(1, STAGE); CPA_COMMIT;

    for (int k = 0; k < 72; k++) {
        u32 cur = (u32)(k % 3) * STAGE;
        if (k < 71) CPA_WAIT1; else CPA_WAIT0;
        __syncthreads();   // chunk k visible to all; all warps done consuming k-1
        if (k < 70) { stage_chunk(k + 2, (u32)((k + 2) % 3) * STAGE); CPA_COMMIT; }

        const u32 Ah = sb + cur;
        const u32 Bh = Ah + 8192u, Bl = Ah + 16384u;
#pragma unroll
        for (int k16 = 0; k16 < 2; k16++) {
            const u32 kb = (u32)k16 << 5;
            u32 ah[4][4], bh[2][4], bl[2][4];
#pragma unroll
            for (int i = 0; i < 4; i++)
                LDSM4(ah[i][0], ah[i][1], ah[i][2], ah[i][3],
                      Ah + sw64(((aRow + i * 16) << 6) + kb + aCol));
#pragma unroll
            for (int g = 0; g < 2; g++)
                LDSM4(bh[g][0], bh[g][1], bh[g][2], bh[g][3],
                      Bh + sw64(((bRow + g * 16) << 6) + kb + bCol));
#pragma unroll
            for (int g = 0; g < 2; g++)
                LDSM4(bl[g][0], bl[g][1], bl[g][2], bl[g][3],
                      Bl + sw64(((bRow + g * 16) << 6) + kb + bCol));
#pragma unroll
            for (int i = 0; i < 4; i++)
#pragma unroll
                for (int j = 0; j < 4; j++) {
                    MMA16816(acc[i][j], ah[i], bh[j >> 1][2 * (j & 1)], bh[j >> 1][2 * (j & 1) + 1]);
                    MMA16816(acc[i][j], ah[i], bl[j >> 1][2 * (j & 1)], bl[j >> 1][2 * (j & 1) + 1]);
                }
        }
    }

    if (MODE == 0) {
        // ---- coalesced epilogue: acc -> smem [px][ch] (swizzled) -> uint4 STG
        fp16* ohi = br ? o1h : o0h;
        fp16* olo = br ? o1l : o0l;
        const float* bias = br ? bias1 : bias0;
        __syncthreads();   // mainloop smem ring now free
#pragma unroll
        for (int i = 0; i < 4; i++) {
            int cl0 = mw * 64 + i * 16 + (lane >> 2);
            float bv0 = bias[co_base + cl0];
            float bv1 = bias[co_base + cl0 + 8];
#pragma unroll
            for (int j = 0; j < 4; j++) {
                int pxb = nw * 32 + j * 8 + ((lane & 3) << 1);
#pragma unroll
                for (int e = 0; e < 4; e++) {
                    int cl = (e < 2) ? cl0 : cl0 + 8;
                    float bv = (e < 2) ? bv0 : bv1;
                    int px = pxb + (e & 1);
                    float xv = fmaxf(acc[i][j][e] + bv, 0.f);
                    fp16 h, l; fp16_split(xv, h, l);
                    u32 off = (u32)px * 256 + (((u32)cl * 2) ^ (((u32)px & 15) << 4));
                    *(fp16*)(smem + off) = h;
                    *(fp16*)(smem + 32768 + off) = l;
                }
            }
        }
        __syncthreads();
#pragma unroll
        for (int ii = 0; ii < 16; ii++) {
            int idx = tid + (ii << 8);
            int plane = idx >> 11;
            int rem = idx & 2047;
            int px  = rem >> 4;
            int seg = rem & 15;
            u32 soff = (u32)plane * 32768 + (u32)px * 256 + (((u32)seg * 16) ^ (((u32)px & 15) << 4));
            uint4 v = *(uint4*)(smem + soff);
            fp16* dst = (plane ? olo : ohi)
                + ((((size_t)b << logHW) + P0 + px) << 8) + co_base + seg * 8;
            *(uint4*)dst = v;
        }
    } else {
        // ---- pred epilogue: scalar fp32 into (B,5376,85)
        const float* bias = br ? bias1 : bias0;
        const int co_off = br ? 80 : 0;
        const int coutA  = br ? 5 : 80;
#pragma unroll
        for (int i = 0; i < 4; i++) {
            int cl0 = mw * 64 + i * 16 + (lane >> 2);
            int cl1 = cl0 + 8;
            float bv0 = (cl0 < coutA) ? bias[cl0] : 0.f;
            float bv1 = (cl1 < coutA) ? bias[cl1] : 0.f;
#pragma unroll
            for (int j = 0; j < 4; j++) {
                int px = P0 + nw * 32 + j * 8 + ((lane & 3) << 1);
#pragma unroll
                for (int e = 0; e < 4; e++) {
                    int cl = (e < 2) ? cl0 : cl1;
                    float bv = (e < 2) ? bv0 : bv1;
                    int p = px + (e & 1);
                    if (cl < coutA)
                        opred[((size_t)b * 5376 + row_off + p) * 85 + co_off + cl] = acc[i][j][e] + bv;
                }
            }
        }
    }
}

// ---------------- host launcher ----------------
extern "C" void kernel_launch(void* const* d_in, const int* in_sizes, int n_in,
                              void* d_out, int out_size)
{
    const float* f[13];
    for (int i = 0; i < 13; i++) f[i] = (const float*)d_in[i];
    float* out = (float*)d_out;

    fp16 *a0, *c1, *c2, *x1, *x2, *wsh, *wph;
    float* b5;
    cudaGetSymbolAddress((void**)&a0, g_act0);
    cudaGetSymbolAddress((void**)&c1, g_c1);
    cudaGetSymbolAddress((void**)&c2, g_c2);
    cudaGetSymbolAddress((void**)&x1, g_x1);
    cudaGetSymbolAddress((void**)&x2, g_x2);
    cudaGetSymbolAddress((void**)&wsh, g_wsh);
    cudaGetSymbolAddress((void**)&wph, g_wph);
    cudaGetSymbolAddress((void**)&b5, g_b5);

    cudaFuncSetAttribute(conv_mma<0>, cudaFuncAttributeMaxDynamicSharedMemorySize, SMEMSZ);
    cudaFuncSetAttribute(conv_mma<1>, cudaFuncAttributeMaxDynamicSharedMemorySize, SMEMSZ);

    // weight/bias prepasses
    pack_b5<<<1, 8>>>(f[10], f[12]);
    conv_stem_w<<<9216, 256>>>(f[3], wsh);                       // cls stems
    conv_stem_w<<<9216, 256>>>(f[5], wsh + 36ul * 65536);        // box stems
    conv_pred_w<<<1152, 256>>>(f[7], 80, nullptr, wph);          // cls pred
    conv_pred_w<<<1152, 256>>>(f[9], 4, f[11], wph + 9ul * 32768); // box+ctr

    struct Lv { const float* feat; int logW, logHW, row_off; };
    const Lv lv[3] = { { f[0], 6, 12, 0 }, { f[1], 5, 10, 4096 }, { f[2], 4, 8, 5120 } };

    for (int l = 0; l < 3; l++) {
        const int logW = lv[l].logW, logHW = lv[l].logHW, row_off = lv[l].row_off;
        const int HW = 1 << logHW;
        to_planes<<<dim3(HW / 32, 8, 16), dim3(32, 8)>>>(lv[l].feat, a0, a0 + PLANE, logHW);

        dim3 gs(HW / 128, 2, 32), gp(HW / 128, 1, 32);
        const size_t WL = 9ul * 65536;   // one stem layer's weight plane
        // layer 0: a0 -> c1 / x1
        conv_mma<0><<<gs, 256, SMEMSZ>>>(wsh + 0 * WL, wsh + 36ul * 65536 + 0 * WL, 256,
            a0, a0 + PLANE, a0, a0 + PLANE, f[4] + 0, f[6] + 0,
            c1, c1 + PLANE, x1, x1 + PLANE, nullptr, logW, logHW, 0);
        // layer 1: c1/x1 -> c2/x2
        conv_mma<0><<<gs, 256, SMEMSZ>>>(wsh + 1 * WL, wsh + 36ul * 65536 + 1 * WL, 256,
            c1, c1 + PLANE, x1, x1 + PLANE, f[4] + 256, f[6] + 256,
            c2, c2 + PLANE, x2, x2 + PLANE, nullptr, logW, logHW, 0);
        // layer 2: c2/x2 -> c1/x1
        conv_mma<0><<<gs, 256, SMEMSZ>>>(wsh + 2 * WL, wsh + 36ul * 65536 + 2 * WL, 256,
            c2, c2 + PLANE, x2, x2 + PLANE, f[4] + 512, f[6] + 512,
            c1, c1 + PLANE, x1, x1 + PLANE, nullptr, logW, logHW, 0);
        // layer 3: c1/x1 -> c2/x2
        conv_mma<0><<<gs, 256, SMEMSZ>>>(wsh + 3 * WL, wsh + 36ul * 65536 + 3 * WL, 256,
            c1, c1 + PLANE, x1, x1 + PLANE, f[4] + 768, f[6] + 768,
            c2, c2 + PLANE, x2, x2 + PLANE, nullptr, logW, logHW, 0);
        // pred: set 0 = cls from c2, set 1 = box+ctr from x2
        conv_mma<1><<<gp, 256, SMEMSZ>>>(wph, wph + 9ul * 32768, 128,
            c2, c2 + PLANE, x2, x2 + PLANE, f[8], b5,
            nullptr, nullptr, nullptr, nullptr, out, logW, logHW, row_off);
    }
}